// round 11
// baseline (speedup 1.0000x reference)
#include <cuda_runtime.h>
#include <cstdint>

#define Bb 8
#define Nn 2048
#define Mm 256
#define Qq 16384
#define Dd 32
#define Rr 16
#define Kk 16
#define Hh 64
#define LAM 5.0f
#define NITER 20
#define RAD 0.005859375f   // 1.5/256 exact in binary

#define NC 16              // CTAs per cluster (per batch)
#define NODES 16           // nodes per CTA
#define VEC (NODES*Dd)     // 512 floats per CTA

// ---------------- scratch (device globals; no allocation allowed) ----------
__device__ float g_c0[Bb*Mm*Dd];
__device__ float g_c [Bb*Mm*Dd];
__device__ float g_gvec[Bb*Dd];

__device__ __forceinline__ float warp_sum(float v) {
#pragma unroll
    for (int o = 16; o; o >>= 1) v += __shfl_xor_sync(0xffffffffu, v, o);
    return v;
}

__device__ __forceinline__ unsigned smem_u32(const void* p) {
    unsigned a;
    asm("{ .reg .u64 t; cvta.to.shared.u64 t, %1; cvt.u32.u64 %0, t; }"
        : "=r"(a) : "l"(p));
    return a;
}

// store 4 bytes into peer CTA (rank) smem at the address corresponding to laddr
__device__ __forceinline__ void st_remote(unsigned laddr, unsigned rank, float v) {
    unsigned r;
    asm volatile("mapa.shared::cluster.u32 %0, %1, %2;" : "=r"(r) : "r"(laddr), "r"(rank));
    asm volatile("st.shared::cluster.f32 [%0], %1;" :: "r"(r), "f"(v) : "memory");
}

__device__ __forceinline__ void cluster_sync_() {
    asm volatile("barrier.cluster.arrive.aligned;" ::: "memory");  // release
    asm volatile("barrier.cluster.wait.aligned;"   ::: "memory");  // acquire
}

// ---------------- kernel 1: global gate vector gvec[b][d] -------------------
__global__ __launch_bounds__(256) void gvec_kernel(
    const float* __restrict__ xs, const float* __restrict__ us,
    const float* __restrict__ Wg1, const float* __restrict__ bg1,
    const float* __restrict__ Wg2, const float* __restrict__ bg2)
{
    __shared__ float sp[4*Hh];
    __shared__ float sg[Hh];
    int b = blockIdx.x, t = threadIdx.x;
    int h = t & 63, grp = t >> 6;
    float w0 = Wg1[h], w1 = Wg1[Hh+h], bb = bg1[h];
    const float* xp = xs + b*Nn;
    const float* up = us + b*Nn;
    float acc = 0.f;
    int n0 = grp * (Nn/4);
    for (int n = n0; n < n0 + Nn/4; n++)
        acc += fmaxf(fmaf(xp[n], w0, fmaf(up[n], w1, bb)), 0.f);
    sp[t] = acc;
    __syncthreads();
    if (t < Hh) sg[t] = (sp[t] + sp[64+t] + sp[128+t] + sp[192+t]) * (1.0f/Nn);
    __syncthreads();
    if (t < Dd) {
        float a = bg2[t];
        for (int hh = 0; hh < Hh; hh++) a = fmaf(sg[hh], Wg2[hh*Dd + t], a);
        g_gvec[b*Dd + t] = a;
    }
}

// ---------------- kernel 2: encoder (low-smem; W2 from L1-resident gmem) ----
__global__ __launch_bounds__(64) void enc_kernel(
    const float* __restrict__ xs, const float* __restrict__ us,
    const float* __restrict__ centers, const int* __restrict__ idx,
    const float* __restrict__ W1, const float* __restrict__ b1,
    const float* __restrict__ W2, const float* __restrict__ b2,
    const float* __restrict__ W3, const float* __restrict__ b3,
    float* __restrict__ out)
{
    __shared__ float sh1[16*68];    // h1[k][i], float4-aligned rows
    __shared__ float srel[16], su[16], sW1[128], shbar[64];
    int m = blockIdx.x, b = blockIdx.y, t = threadIdx.x;

    for (int i = t; i < 128; i += 64) sW1[i] = W1[i];
    if (t < 16) {
        int sidx = idx[m*Kk + t];
        srel[t] = (xs[b*Nn + sidx] - centers[m]) / RAD;
        su[t]   = us[b*Nn + sidx];
    }
    __syncthreads();

    {   // h1: thread t = hidden unit i
        float wa = sW1[t], wb = sW1[64+t], bb = b1[t];
#pragma unroll
        for (int k = 0; k < 16; k++)
            sh1[k*68 + t] = fmaxf(fmaf(srel[k], wa, fmaf(su[k], wb, bb)), 0.f);
    }
    __syncthreads();

    {   // h2 = relu(h1 @ W2 + b2); mean over k.  W2 columns via coalesced LDG.
        float acc[16];
        float bb = b2[t];
#pragma unroll
        for (int k = 0; k < 16; k++) acc[k] = bb;
#pragma unroll 4
        for (int i = 0; i < 64; i += 4) {
            float w0 = __ldg(&W2[(i+0)*64 + t]);
            float w1 = __ldg(&W2[(i+1)*64 + t]);
            float w2 = __ldg(&W2[(i+2)*64 + t]);
            float w3 = __ldg(&W2[(i+3)*64 + t]);
#pragma unroll
            for (int k = 0; k < 16; k++) {
                float4 hq = *(const float4*)&sh1[k*68 + i];
                acc[k] = fmaf(hq.x, w0, acc[k]);
                acc[k] = fmaf(hq.y, w1, acc[k]);
                acc[k] = fmaf(hq.z, w2, acc[k]);
                acc[k] = fmaf(hq.w, w3, acc[k]);
            }
        }
        float s = 0.f;
#pragma unroll
        for (int k = 0; k < 16; k++) s += fmaxf(acc[k], 0.f);
        shbar[t] = s * 0.0625f;
    }
    __syncthreads();

    if (t < 32) {
        float v = b3[t];
        for (int j = 0; j < 64; j++) v = fmaf(shbar[j], W3[j*Dd + t], v);
        v += g_gvec[b*Dd + t];
        int o = (b*Mm + m)*Dd + t;
        g_c0[o] = v;
        out[Bb*Qq + o] = v;   // c0 output segment
    }
}

// ---------------- CG: sheaf Laplacian edge pass (R tiles in smem) -----------
__device__ __forceinline__ void edge_pass(
    const float* __restrict__ sRS, const float* __restrict__ sRD,
    const float* __restrict__ sP, float* __restrict__ sGs, float* __restrict__ sGd,
    float* __restrict__ sRe, int nE, int wid, int lane)
{
    int rho = lane >> 1, h = lane & 1;
    int d = lane;
    for (int el = wid; el < nE; el += 16) {
        const float* bs = sRS + el*528;
        const float* bd = sRD + el*528;
        const float* ps = sP + el*32 + 16*h;     // src half; dst at +32
        const float* rs_ = bs + rho*33 + 16*h;
        const float* rd_ = bd + rho*33 + 16*h;
        float a0 = 0.f, a1 = 0.f, a2 = 0.f, a3 = 0.f;
#pragma unroll
        for (int i = 0; i < 16; i += 4) {
            a0 = fmaf(rs_[i+0], ps[i+0], a0);
            a1 = fmaf(rs_[i+1], ps[i+1], a1);
            a2 = fmaf(rs_[i+2], ps[i+2], a2);
            a3 = fmaf(rs_[i+3], ps[i+3], a3);
            a0 = fmaf(rd_[i+0], -ps[32+i+0], a0);
            a1 = fmaf(rd_[i+1], -ps[32+i+1], a1);
            a2 = fmaf(rd_[i+2], -ps[32+i+2], a2);
            a3 = fmaf(rd_[i+3], -ps[32+i+3], a3);
        }
        float acc = (a0 + a1) + (a2 + a3);
        acc += __shfl_xor_sync(0xffffffffu, acc, 1);
        if (h == 0) sRe[el*16 + rho] = acc;
        __syncwarp();

        float g0 = 0.f, g1 = 0.f, q0a = 0.f, q1a = 0.f;
#pragma unroll
        for (int q = 0; q < 16; q += 2) {
            float r0v = sRe[el*16 + q];
            float r1v = sRe[el*16 + q + 1];
            g0  = fmaf(bs[q*33 + d],       r0v, g0);
            g1  = fmaf(bs[(q+1)*33 + d],   r1v, g1);
            q0a = fmaf(bd[q*33 + d],       r0v, q0a);
            q1a = fmaf(bd[(q+1)*33 + d],   r1v, q1a);
        }
        sGs[el*32 + d] = g0 + g1;
        sGd[el*32 + d] = q0a + q1a;
    }
}

// ---------------- kernel 3: persistent cluster CG (8 clusters x 16 CTAs) ----
// smem layout (float offsets); max nE = 17, max nExt = 18
#define SM_RS  0                        // 17*528 = 8976
#define SM_RD  8976                     // 8976
#define SM_P   17952                    // 18*32 = 576
#define SM_X   (SM_P + 576)             // 512
#define SM_R   (SM_X + 512)             // 512
#define SM_AP  (SM_R + 512)             // 512
#define SM_GS  (SM_AP + 512)            // 17*32 = 544
#define SM_GD  (SM_GS + 544)            // 544
#define SM_RE  (SM_GD + 544)            // 17*16 = 272
#define SM_RED (SM_RE + 272)            // 16 warp partials
#define SM_S0  (SM_RED + 16)            // incoming rs partials [16]
#define SM_S1  (SM_S0 + 16)             // incoming pAp partials [16]
#define SM_HL  (SM_S1 + 16)             // incoming left-halo r [32]
#define SM_HR  (SM_HL + 32)             // incoming right-halo r [32]
#define SM_TOT_FLOATS (SM_HR + 32)
#define SMEM_CG_BYTES (SM_TOT_FLOATS * 4)

__global__ __launch_bounds__(512, 1)
void cg_kernel(const float* __restrict__ Rsrc, const float* __restrict__ Rdst,
               float* __restrict__ out)
{
    extern __shared__ float sm[];
    float* sRS  = sm + SM_RS;
    float* sRD  = sm + SM_RD;
    float* sP   = sm + SM_P;
    float* sX   = sm + SM_X;
    float* sR   = sm + SM_R;
    float* sAp  = sm + SM_AP;
    float* sGs  = sm + SM_GS;
    float* sGd  = sm + SM_GD;
    float* sRe  = sm + SM_RE;
    float* sRed = sm + SM_RED;
    float* sS0  = sm + SM_S0;
    float* sS1  = sm + SM_S1;
    float* sHL  = sm + SM_HL;
    float* sHR  = sm + SM_HR;

    int t = threadIdx.x, wid = t >> 5, lane = t & 31;
    int blk = blockIdx.x;
    int b = blk >> 4, c = blk & 15;         // cluster = batch, rank = c
    int m0 = c * NODES;
    int mLo = (c > 0) ? m0 - 1 : 0;
    int eLo = (c > 0) ? m0 - 1 : 0;
    int eHi = (c < NC-1) ? m0 + NODES - 1 : Mm - 2;
    int nE = eHi - eLo + 1;                 // 16 or 17
    int mHi = (c < NC-1) ? m0 + NODES : Mm - 1;
    int nExt = mHi - mLo + 1;               // up to 18
    int ownOff = (m0 - mLo) * 32;

    unsigned smb = smem_u32(sm);
    unsigned aS0 = smb + (SM_S0 + c) * 4;   // slot c in peers' rs array
    unsigned aS1 = smb + (SM_S1 + c) * 4;   // slot c in peers' pAp array
    unsigned aHL = smb + SM_HL * 4;
    unsigned aHR = smb + SM_HR * 4;

    // ---- load R tiles into padded smem (resident for all iterations) ----
    for (int i = t; i < nE*512; i += 512) {
        int el = i >> 9, rem = i & 511;
        int rho = rem >> 5, d = rem & 31;
        int g = (eLo + el)*512 + rem;
        sRS[el*528 + rho*33 + d] = Rsrc[g];
        sRD[el*528 + rho*33 + d] = Rdst[g];
    }
    const float* c0b = g_c0 + b*Mm*Dd;
    for (int i = t; i < nExt*32; i += 512) sP[i] = c0b[mLo*32 + i];
    __syncthreads();
    if (t < VEC) sX[t] = sP[ownOff + t];

    // ---- prologue: r0 = -LAM * L(c0) ----
    edge_pass(sRS, sRD, sP, sGs, sGd, sRe, nE, wid, lane);
    __syncthreads();
    {
        float part = 0.f;
        if (t < VEC) {
            int d = t & 31;
            int m = m0 + (t >> 5);
            float gs = (m <= Mm-2) ? sGs[(m - eLo)*32 + d] : 0.f;
            float gd = (m >= 1)    ? sGd[(m - 1 - eLo)*32 + d] : 0.f;
            float rv = -LAM * (gs - gd);
            sR[t] = rv;
            part = rv * rv;
        }
        part = warp_sum(part);
        if (lane == 0) sRed[wid] = part;
    }
    __syncthreads();
    // push rs partials to all ranks + r halos to neighbors
    if (t < NC) {
        float tot = 0.f;
#pragma unroll
        for (int j = 0; j < 16; j++) tot += sRed[j];
        st_remote(aS0, (unsigned)t, tot);
    }
    if (c > 0 && t < 32)                  st_remote(aHR + t*4, (unsigned)(c-1), sR[t]);
    if (c < NC-1 && t >= 32 && t < 64) {  int l = t - 32;
                                          st_remote(aHL + l*4, (unsigned)(c+1), sR[(NODES-1)*32 + l]); }
    cluster_sync_();

    float rs_prev = 1.f;
    for (int k = 0; k < NITER; k++) {
        // ---- phase A: beta, p update, Ap, partial p.Ap ----
        float rs_k = 0.f;
#pragma unroll
        for (int j = 0; j < 16; j++) rs_k += sS0[j];
        float beta = (k == 0) ? 0.f : rs_k / (rs_prev + 1e-12f);

        if (t < VEC)
            sP[ownOff + t] = fmaf(beta, sP[ownOff + t], sR[t]);
        if (c > 0 && t < 32)
            sP[t] = fmaf(beta, sP[t], sHL[t]);
        if (c < NC-1 && t >= 32 && t < 64) { int l = t - 32;
            sP[(nExt-1)*32 + l] = fmaf(beta, sP[(nExt-1)*32 + l], sHR[l]); }
        __syncthreads();
        edge_pass(sRS, sRD, sP, sGs, sGd, sRe, nE, wid, lane);
        __syncthreads();
        {
            float pap = 0.f;
            if (t < VEC) {
                int d = t & 31;
                int m = m0 + (t >> 5);
                float gs = (m <= Mm-2) ? sGs[(m - eLo)*32 + d] : 0.f;
                float gd = (m >= 1)    ? sGd[(m - 1 - eLo)*32 + d] : 0.f;
                float pv = sP[ownOff + t];
                float ap = fmaf(LAM, gs - gd, pv);
                sAp[t] = ap;
                pap = ap * pv;
            }
            pap = warp_sum(pap);
            if (lane == 0) sRed[wid] = pap;
        }
        __syncthreads();
        if (t < NC) {
            float tot = 0.f;
#pragma unroll
            for (int j = 0; j < 16; j++) tot += sRed[j];
            st_remote(aS1, (unsigned)t, tot);
        }
        cluster_sync_();

        // ---- phase B: alpha, x/r update, partial ||r||^2, push rs + halo ----
        float pap_tot = 0.f;
#pragma unroll
        for (int j = 0; j < 16; j++) pap_tot += sS1[j];
        float alpha = rs_k / (pap_tot + 1e-12f);
        {
            float rp = 0.f;
            if (t < VEC) {
                sX[t] = fmaf(alpha, sP[ownOff + t], sX[t]);
                float rv = fmaf(-alpha, sAp[t], sR[t]);
                sR[t] = rv;
                rp = rv * rv;
            }
            rp = warp_sum(rp);
            if (lane == 0) sRed[wid] = rp;
        }
        __syncthreads();
        if (t < NC) {
            float tot = 0.f;
#pragma unroll
            for (int j = 0; j < 16; j++) tot += sRed[j];
            st_remote(aS0, (unsigned)t, tot);
        }
        if (c > 0 && t < 32)                  st_remote(aHR + t*4, (unsigned)(c-1), sR[t]);
        if (c < NC-1 && t >= 32 && t < 64) {  int l = t - 32;
                                              st_remote(aHL + l*4, (unsigned)(c+1), sR[(NODES-1)*32 + l]); }
        rs_prev = rs_k;
        cluster_sync_();
    }

    // final x -> g_c and out c segment
    if (t < VEC) {
        float v = sX[t];
        int o = (b*Mm + m0)*32 + t;
        g_c[o] = v;
        out[Bb*Qq + Bb*Mm*Dd + o] = v;
    }
}

// ---------------- kernel 4: sparse decode (constant 3-trip, 8 thr/q) --------
__global__ __launch_bounds__(256) void dec_kernel(
    const float* __restrict__ phi, const float* __restrict__ w,
    float* __restrict__ out)
{
    __shared__ float sc[3*8*32];
    __shared__ float sw[3*32];
    int blk = blockIdx.x, t = threadIdx.x;
    int q0 = blk * 32;
    int g = blk >> 1;                  // 64-q group shares an m-center
    // constant 3 m-slots: m = g-1, g, g+1 clamped; invalid slots get w=0
    for (int i = t; i < 3*256; i += 256) {
        int mi = i >> 8, rem = i & 255;
        int mm = min(max(g - 1 + mi, 0), Mm - 1);
        sc[i] = g_c[((rem >> 5)*Mm + mm)*Dd + (rem & 31)];
    }
    if (t < 96) {
        int mi = t >> 5, ql = t & 31;
        int mme = g - 1 + mi;
        sw[t] = (mme >= 0 && mme < Mm) ? w[mme*Qq + q0 + ql] : 0.f;
    }
    __syncthreads();

    int ql = t >> 3, dq = t & 7;       // 8 threads per q, 4 d each
    int q = q0 + ql;
    float s[8];
#pragma unroll
    for (int bidx = 0; bidx < 8; bidx++) s[bidx] = 0.f;

#pragma unroll
    for (int mi = 0; mi < 3; mi++) {
        int mm = min(max(g - 1 + mi, 0), Mm - 1);
        const float* ph = phi + ((size_t)mm*Qq + q)*Dd + dq*4;
        float4 p0 = *(const float4*)ph;
        float wq = sw[mi*32 + ql];
#pragma unroll
        for (int bidx = 0; bidx < 8; bidx++) {
            const float* cc = &sc[(mi*8 + bidx)*32 + dq*4];
            float dot = p0.x*cc[0] + p0.y*cc[1] + p0.z*cc[2] + p0.w*cc[3];
            s[bidx] = fmaf(wq, dot, s[bidx]);
        }
    }
#pragma unroll
    for (int bidx = 0; bidx < 8; bidx++) {
        s[bidx] += __shfl_xor_sync(0xffffffffu, s[bidx], 1);
        s[bidx] += __shfl_xor_sync(0xffffffffu, s[bidx], 2);
        s[bidx] += __shfl_xor_sync(0xffffffffu, s[bidx], 4);
    }
    if (dq == 0) {
#pragma unroll
        for (int bidx = 0; bidx < 8; bidx++)
            out[bidx*Qq + q] = s[bidx];
    }
}

// ---------------- launch ----------------------------------------------------
extern "C" void kernel_launch(void* const* d_in, const int* in_sizes, int n_in,
                              void* d_out, int out_size)
{
    (void)in_sizes; (void)n_in; (void)out_size;
    const float* xs      = (const float*)d_in[0];
    const float* us      = (const float*)d_in[1];
    const float* phi     = (const float*)d_in[2];
    const float* w       = (const float*)d_in[3];
    const float* centers = (const float*)d_in[4];
    const float* Rsrc    = (const float*)d_in[5];
    const float* Rdst    = (const float*)d_in[6];
    const float* W1      = (const float*)d_in[7];
    const float* b1      = (const float*)d_in[8];
    const float* W2      = (const float*)d_in[9];
    const float* b2      = (const float*)d_in[10];
    const float* W3      = (const float*)d_in[11];
    const float* b3      = (const float*)d_in[12];
    const float* Wg1     = (const float*)d_in[13];
    const float* bg1     = (const float*)d_in[14];
    const float* Wg2     = (const float*)d_in[15];
    const float* bg2     = (const float*)d_in[16];
    const int*   idx     = (const int*)d_in[17];
    float* out = (float*)d_out;

    cudaFuncSetAttribute(cg_kernel, cudaFuncAttributeMaxDynamicSharedMemorySize,
                         SMEM_CG_BYTES);
    cudaFuncSetAttribute(cg_kernel, cudaFuncAttributeNonPortableClusterSizeAllowed, 1);

    gvec_kernel<<<Bb, 256>>>(xs, us, Wg1, bg1, Wg2, bg2);
    enc_kernel<<<dim3(Mm, Bb), 64>>>(xs, us, centers, idx,
                                     W1, b1, W2, b2, W3, b3, out);

    {   // 16-CTA clusters: launch-time cluster attribute
        cudaLaunchConfig_t cfg = {};
        cfg.gridDim = dim3(Bb*NC, 1, 1);
        cfg.blockDim = dim3(512, 1, 1);
        cfg.dynamicSmemBytes = SMEM_CG_BYTES;
        cudaLaunchAttribute attrs[1];
        attrs[0].id = cudaLaunchAttributeClusterDimension;
        attrs[0].val.clusterDim = {NC, 1, 1};
        cfg.attrs = attrs;
        cfg.numAttrs = 1;
        cudaLaunchKernelEx(&cfg, cg_kernel, Rsrc, Rdst, out);
    }

    dec_kernel<<<Qq/32, 256>>>(phi, w, out);
}

// round 12
// speedup vs baseline: 1.4609x; 1.4609x over previous
#include <cuda_runtime.h>
#include <cstdint>

#define Bb 8
#define Nn 2048
#define Mm 256
#define Qq 16384
#define Dd 32
#define Rr 16
#define Kk 16
#define Hh 64
#define LAM 5.0f
#define NITER 20
#define RAD 0.005859375f   // 1.5/256 exact in binary

// ---------------- scratch (device globals; no allocation allowed) ----------
__device__ float g_c0[Bb*Mm*Dd];
__device__ float g_c [Bb*Mm*Dd];
__device__ float g_gvec[Bb*Dd];

__device__ __forceinline__ float warp_sum(float v) {
#pragma unroll
    for (int o = 16; o; o >>= 1) v += __shfl_xor_sync(0xffffffffu, v, o);
    return v;
}

__device__ __forceinline__ unsigned smem_u32(const void* p) {
    unsigned a;
    asm("{ .reg .u64 t; cvta.to.shared.u64 t, %1; cvt.u32.u64 %0, t; }"
        : "=r"(a) : "l"(p));
    return a;
}

// store 4 bytes into peer CTA (rank) smem at the address corresponding to laddr
__device__ __forceinline__ void st_remote(unsigned laddr, unsigned rank, float v) {
    unsigned r;
    asm volatile("mapa.shared::cluster.u32 %0, %1, %2;" : "=r"(r) : "r"(laddr), "r"(rank));
    asm volatile("st.shared::cluster.f32 [%0], %1;" :: "r"(r), "f"(v) : "memory");
}

__device__ __forceinline__ void cluster_sync_() {
    asm volatile("barrier.cluster.arrive.aligned;" ::: "memory");  // release
    asm volatile("barrier.cluster.wait.aligned;"   ::: "memory");  // acquire
}

// ---------------- kernel 1: global gate vector gvec[b][d] -------------------
__global__ __launch_bounds__(256) void gvec_kernel(
    const float* __restrict__ xs, const float* __restrict__ us,
    const float* __restrict__ Wg1, const float* __restrict__ bg1,
    const float* __restrict__ Wg2, const float* __restrict__ bg2)
{
    __shared__ float sp[4*Hh];
    __shared__ float sg[Hh];
    int b = blockIdx.x, t = threadIdx.x;
    int h = t & 63, grp = t >> 6;
    float w0 = Wg1[h], w1 = Wg1[Hh+h], bb = bg1[h];
    const float* xp = xs + b*Nn;
    const float* up = us + b*Nn;
    float acc = 0.f;
    int n0 = grp * (Nn/4);
    for (int n = n0; n < n0 + Nn/4; n++)
        acc += fmaxf(fmaf(xp[n], w0, fmaf(up[n], w1, bb)), 0.f);
    sp[t] = acc;
    __syncthreads();
    if (t < Hh) sg[t] = (sp[t] + sp[64+t] + sp[128+t] + sp[192+t]) * (1.0f/Nn);
    __syncthreads();
    if (t < Dd) {
        float a = bg2[t];
        for (int hh = 0; hh < Hh; hh++) a = fmaf(sg[hh], Wg2[hh*Dd + t], a);
        g_gvec[b*Dd + t] = a;
    }
}

// ---------------- kernel 2: encoder (low-smem; W2 from L1-resident gmem) ----
__global__ __launch_bounds__(64) void enc_kernel(
    const float* __restrict__ xs, const float* __restrict__ us,
    const float* __restrict__ centers, const int* __restrict__ idx,
    const float* __restrict__ W1, const float* __restrict__ b1,
    const float* __restrict__ W2, const float* __restrict__ b2,
    const float* __restrict__ W3, const float* __restrict__ b3,
    float* __restrict__ out)
{
    __shared__ float sh1[16*68];    // h1[k][i], float4-aligned rows
    __shared__ float srel[16], su[16], sW1[128], shbar[64];
    int m = blockIdx.x, b = blockIdx.y, t = threadIdx.x;

    for (int i = t; i < 128; i += 64) sW1[i] = W1[i];
    if (t < 16) {
        int sidx = idx[m*Kk + t];
        srel[t] = (xs[b*Nn + sidx] - centers[m]) / RAD;
        su[t]   = us[b*Nn + sidx];
    }
    __syncthreads();

    {   // h1: thread t = hidden unit i
        float wa = sW1[t], wb = sW1[64+t], bb = b1[t];
#pragma unroll
        for (int k = 0; k < 16; k++)
            sh1[k*68 + t] = fmaxf(fmaf(srel[k], wa, fmaf(su[k], wb, bb)), 0.f);
    }
    __syncthreads();

    {   // h2 = relu(h1 @ W2 + b2); mean over k.  W2 columns via coalesced LDG.
        float acc[16];
        float bb = b2[t];
#pragma unroll
        for (int k = 0; k < 16; k++) acc[k] = bb;
#pragma unroll 4
        for (int i = 0; i < 64; i += 4) {
            float w0 = __ldg(&W2[(i+0)*64 + t]);
            float w1 = __ldg(&W2[(i+1)*64 + t]);
            float w2 = __ldg(&W2[(i+2)*64 + t]);
            float w3 = __ldg(&W2[(i+3)*64 + t]);
#pragma unroll
            for (int k = 0; k < 16; k++) {
                float4 hq = *(const float4*)&sh1[k*68 + i];
                acc[k] = fmaf(hq.x, w0, acc[k]);
                acc[k] = fmaf(hq.y, w1, acc[k]);
                acc[k] = fmaf(hq.z, w2, acc[k]);
                acc[k] = fmaf(hq.w, w3, acc[k]);
            }
        }
        float s = 0.f;
#pragma unroll
        for (int k = 0; k < 16; k++) s += fmaxf(acc[k], 0.f);
        shbar[t] = s * 0.0625f;
    }
    __syncthreads();

    if (t < 32) {
        float v = b3[t];
        for (int j = 0; j < 64; j++) v = fmaf(shbar[j], W3[j*Dd + t], v);
        v += g_gvec[b*Dd + t];
        int o = (b*Mm + m)*Dd + t;
        g_c0[o] = v;
        out[Bb*Qq + o] = v;   // c0 output segment
    }
}

// ---------------- CG: sheaf Laplacian edge pass (R tiles in smem) -----------
__device__ __forceinline__ void edge_pass(
    const float* __restrict__ sRS, const float* __restrict__ sRD,
    const float* __restrict__ sV, float* __restrict__ sGs, float* __restrict__ sGd,
    float* __restrict__ sRe, int nE, int wid, int lane)
{
    int rho = lane >> 1, h = lane & 1;
    int d = lane;
    for (int el = wid; el < nE; el += 16) {
        const float* bs = sRS + el*528;
        const float* bd = sRD + el*528;
        const float* ps = sV + el*32 + 16*h;     // src half; dst at +32
        const float* rs_ = bs + rho*33 + 16*h;
        const float* rd_ = bd + rho*33 + 16*h;
        float a0 = 0.f, a1 = 0.f, a2 = 0.f, a3 = 0.f;
#pragma unroll
        for (int i = 0; i < 16; i += 4) {
            a0 = fmaf(rs_[i+0], ps[i+0], a0);
            a1 = fmaf(rs_[i+1], ps[i+1], a1);
            a2 = fmaf(rs_[i+2], ps[i+2], a2);
            a3 = fmaf(rs_[i+3], ps[i+3], a3);
            a0 = fmaf(rd_[i+0], -ps[32+i+0], a0);
            a1 = fmaf(rd_[i+1], -ps[32+i+1], a1);
            a2 = fmaf(rd_[i+2], -ps[32+i+2], a2);
            a3 = fmaf(rd_[i+3], -ps[32+i+3], a3);
        }
        float acc = (a0 + a1) + (a2 + a3);
        acc += __shfl_xor_sync(0xffffffffu, acc, 1);
        if (h == 0) sRe[el*16 + rho] = acc;
        __syncwarp();

        float g0 = 0.f, g1 = 0.f, q0a = 0.f, q1a = 0.f;
#pragma unroll
        for (int q = 0; q < 16; q += 2) {
            float r0v = sRe[el*16 + q];
            float r1v = sRe[el*16 + q + 1];
            g0  = fmaf(bs[q*33 + d],       r0v, g0);
            g1  = fmaf(bs[(q+1)*33 + d],   r1v, g1);
            q0a = fmaf(bd[q*33 + d],       r0v, q0a);
            q1a = fmaf(bd[(q+1)*33 + d],   r1v, q1a);
        }
        sGs[el*32 + d] = g0 + g1;
        sGd[el*32 + d] = q0a + q1a;
    }
}

// ---------------- kernel 3: single-sync CG-CG (8 clusters x 8 CTAs) ---------
// smem layout (float offsets); nE <= 33, nExt <= 34
#define SM_RS  0                        // 33*528 = 17424
#define SM_RD  17424
#define SM_RV  34848                    // r extended, 34*32 = 1088
#define SM_W   (SM_RV + 1088)           // w own, 1024
#define SM_S   (SM_W + 1024)            // s extended, 1088
#define SM_PP  (SM_S + 1088)            // p own, 1024
#define SM_X   (SM_PP + 1024)           // x own, 1024
#define SM_GS  (SM_X + 1024)            // 33*32 = 1056
#define SM_GD  (SM_GS + 1056)           // 1056
#define SM_RE  (SM_GD + 1056)           // 33*16 = 528
#define SM_RED (SM_RE + 528)            // 16 gamma + 16 delta warp partials
#define SM_SC  (SM_RED + 32)            // [par][g/d][8] = 32
#define SM_WH  (SM_SC + 32)             // [par][L/R][32] = 128
#define SM_TOT_FLOATS (SM_WH + 128)
#define SMEM_CG_BYTES (SM_TOT_FLOATS * 4)

__global__ __launch_bounds__(512, 1) __cluster_dims__(8, 1, 1)
void cg_kernel(const float* __restrict__ Rsrc, const float* __restrict__ Rdst,
               float* __restrict__ out)
{
    extern __shared__ float sm[];
    float* sRS  = sm + SM_RS;
    float* sRD  = sm + SM_RD;
    float* sRV  = sm + SM_RV;
    float* sW   = sm + SM_W;
    float* sS   = sm + SM_S;
    float* sPP  = sm + SM_PP;
    float* sX   = sm + SM_X;
    float* sGs  = sm + SM_GS;
    float* sGd  = sm + SM_GD;
    float* sRe  = sm + SM_RE;
    float* sRed = sm + SM_RED;

    int t = threadIdx.x, wid = t >> 5, lane = t & 31;
    int blk = blockIdx.x;
    int b = blk >> 3, c = blk & 7;          // cluster = batch, rank = c
    int m0 = c * 32;
    int mLo = (c > 0) ? m0 - 1 : 0;
    int eLo = (c > 0) ? m0 - 1 : 0;
    int eHi = (c < 7) ? m0 + 31 : 254;
    int nE = eHi - eLo + 1;                 // 32 or 33
    int nExt = 32 + (c > 0 ? 1 : 0) + (c < 7 ? 1 : 0);
    int ownOff = (c > 0) ? 32 : 0;
    int rhOff = ownOff + 1024;              // right-halo offset in extended bufs

    unsigned smb = smem_u32(sm);

    // ---- load R tiles into padded smem (resident for all iterations) ----
    for (int i = t; i < nE*512; i += 512) {
        int el = i >> 9, rem = i & 511;
        int rho = rem >> 5, d = rem & 31;
        int g = (eLo + el)*512 + rem;
        sRS[el*528 + rho*33 + d] = Rsrc[g];
        sRD[el*528 + rho*33 + d] = Rdst[g];
    }
    // c0 extended into sRV
    const float* c0b = g_c0 + b*Mm*Dd;
    for (int i = t; i < nExt*32; i += 512) sRV[i] = c0b[mLo*32 + i];
    __syncthreads();

    // ---- prologue: r0 = -LAM * L(c0) (own); x = c0 (own) ----
    edge_pass(sRS, sRD, sRV, sGs, sGd, sRe, nE, wid, lane);
    __syncthreads();
    for (int i = t; i < 1024; i += 512) {
        int dd = i & 31, m = m0 + (i >> 5);
        float gs = (m <= Mm-2) ? sGs[(m - eLo)*32 + dd] : 0.f;
        float gd = (m >= 1)    ? sGd[(m - 1 - eLo)*32 + dd] : 0.f;
        sX[i] = sRV[ownOff + i];            // x = c0
        sRV[ownOff + i] = -LAM * (gs - gd); // r0
    }
    __syncthreads();
    // push r0 boundary rows into neighbors' WH parity-1 slots
    if (c > 0 && t < 32)
        st_remote(smb + (SM_WH + 64 + 32 + t)*4, (unsigned)(c-1), sRV[ownOff + t]);
    if (c < 7 && t >= 32 && t < 64) { int l = t - 32;
        st_remote(smb + (SM_WH + 64 + l)*4, (unsigned)(c+1), sRV[ownOff + 31*32 + l]); }
    cluster_sync_();
    // copy received r0 halos into extended r
    if (c > 0 && t < 32)               sRV[t] = sm[SM_WH + 64 + t];
    if (c < 7 && t >= 32 && t < 64) {  int l = t - 32;
                                       sRV[rhOff + l] = sm[SM_WH + 64 + 32 + l]; }
    __syncthreads();

    float gamma_prev = 1.f, alpha_prev = 1.f;
    for (int k = 0; k < NITER; k++) {
        int par = k & 1;
        // ---- w = A r (own nodes) ----
        edge_pass(sRS, sRD, sRV, sGs, sGd, sRe, nE, wid, lane);
        __syncthreads();
        {
            float g = 0.f, d = 0.f;
            for (int i = t; i < 1024; i += 512) {
                int dd = i & 31, m = m0 + (i >> 5);
                float gs = (m <= Mm-2) ? sGs[(m - eLo)*32 + dd] : 0.f;
                float gd = (m >= 1)    ? sGd[(m - 1 - eLo)*32 + dd] : 0.f;
                float rv = sRV[ownOff + i];
                float wv = fmaf(LAM, gs - gd, rv);
                sW[i] = wv;
                g = fmaf(rv, rv, g);
                d = fmaf(rv, wv, d);
            }
            g = warp_sum(g); d = warp_sum(d);
            if (lane == 0) { sRed[wid] = g; sRed[16 + wid] = d; }
        }
        __syncthreads();
        // ---- pushes: scalars to all ranks; w boundary rows to neighbors ----
        if (t < 8) {
            float tot = 0.f;
#pragma unroll
            for (int j = 0; j < 16; j++) tot += sRed[j];
            st_remote(smb + (SM_SC + par*16 + c)*4, (unsigned)t, tot);
        } else if (t < 16) {
            float tot = 0.f;
#pragma unroll
            for (int j = 0; j < 16; j++) tot += sRed[16 + j];
            st_remote(smb + (SM_SC + par*16 + 8 + c)*4, (unsigned)(t - 8), tot);
        }
        if (c > 0 && t >= 64 && t < 96) { int l = t - 64;
            st_remote(smb + (SM_WH + par*64 + 32 + l)*4, (unsigned)(c-1), sW[l]); }
        if (c < 7 && t >= 96 && t < 128) { int l = t - 96;
            st_remote(smb + (SM_WH + par*64 + l)*4, (unsigned)(c+1), sW[31*32 + l]); }
        cluster_sync_();

        // ---- scalars (identical on all CTAs) ----
        float gamma = 0.f, delta = 0.f;
#pragma unroll
        for (int j = 0; j < 8; j++) { gamma += sm[SM_SC + par*16 + j];
                                      delta += sm[SM_SC + par*16 + 8 + j]; }
        float beta  = (k == 0) ? 0.f : gamma / (gamma_prev + 1e-12f);
        float den   = (k == 0) ? delta : delta - beta * gamma / alpha_prev;
        float alpha = gamma / (den + 1e-12f);

        // ---- local updates: s,r extended; p,x own ----
        for (int i = t; i < nExt*32; i += 512) {
            int io = i - ownOff;
            float wv;
            if (io >= 0 && io < 1024)      wv = sW[io];
            else if (io < 0)               wv = sm[SM_WH + par*64 + i];
            else                           wv = sm[SM_WH + par*64 + 32 + (io - 1024)];
            float sv = (k == 0) ? wv : fmaf(beta, sS[i], wv);
            sS[i] = sv;
            if (io >= 0 && io < 1024) {
                float rold = sRV[i];
                float pv = (k == 0) ? rold : fmaf(beta, sPP[io], rold);
                sPP[io] = pv;
                sX[io] = fmaf(alpha, pv, sX[io]);
            }
            sRV[i] = fmaf(-alpha, sv, sRV[i]);
        }
        __syncthreads();

        gamma_prev = gamma;
        alpha_prev = alpha;
    }

    // final x -> g_c and out c segment
    for (int i = t; i < 1024; i += 512) {
        float v = sX[i];
        int o = (b*Mm + m0)*32 + i;
        g_c[o] = v;
        out[Bb*Qq + Bb*Mm*Dd + o] = v;
    }
}

// ---------------- kernel 4: sparse decode (3-neighborhood, 8 thr/q) ---------
__global__ __launch_bounds__(256) void dec_kernel(
    const float* __restrict__ phi, const float* __restrict__ w,
    float* __restrict__ out)
{
    __shared__ float sc[3*8*32];
    __shared__ float sw[3*32];
    int blk = blockIdx.x, t = threadIdx.x;
    int q0 = blk * 32;
    int g = blk >> 1;                  // 64-q group shares an m-center
    int mlist[3]; int nm = 0;
#pragma unroll
    for (int dm = -1; dm <= 1; dm++) {
        int mm = g + dm;
        if (mm >= 0 && mm < Mm) mlist[nm++] = mm;
    }
    for (int i = t; i < nm*256; i += 256) {
        int mi = i >> 8, rem = i & 255;
        int bidx = rem >> 5, d = rem & 31;
        sc[i] = g_c[(bidx*Mm + mlist[mi])*Dd + d];
    }
    if (t < nm*32) {
        int mi = t >> 5, ql = t & 31;
        sw[t] = w[mlist[mi]*Qq + q0 + ql];
    }
    __syncthreads();

    int ql = t >> 3, dq = t & 7;       // 8 threads per q, 4 d each
    int q = q0 + ql;
    float s[8];
#pragma unroll
    for (int bidx = 0; bidx < 8; bidx++) s[bidx] = 0.f;

    for (int mi = 0; mi < nm; mi++) {
        const float* ph = phi + ((size_t)mlist[mi]*Qq + q)*Dd + dq*4;
        float4 p0 = *(const float4*)ph;
        float wq = sw[mi*32 + ql];
#pragma unroll
        for (int bidx = 0; bidx < 8; bidx++) {
            const float* cc = &sc[(mi*8 + bidx)*32 + dq*4];
            float dot = p0.x*cc[0] + p0.y*cc[1] + p0.z*cc[2] + p0.w*cc[3];
            s[bidx] = fmaf(wq, dot, s[bidx]);
        }
    }
#pragma unroll
    for (int bidx = 0; bidx < 8; bidx++) {
        s[bidx] += __shfl_xor_sync(0xffffffffu, s[bidx], 1);
        s[bidx] += __shfl_xor_sync(0xffffffffu, s[bidx], 2);
        s[bidx] += __shfl_xor_sync(0xffffffffu, s[bidx], 4);
    }
    if (dq == 0) {
#pragma unroll
        for (int bidx = 0; bidx < 8; bidx++)
            out[bidx*Qq + q] = s[bidx];
    }
}

// ---------------- launch ----------------------------------------------------
extern "C" void kernel_launch(void* const* d_in, const int* in_sizes, int n_in,
                              void* d_out, int out_size)
{
    (void)in_sizes; (void)n_in; (void)out_size;
    const float* xs      = (const float*)d_in[0];
    const float* us      = (const float*)d_in[1];
    const float* phi     = (const float*)d_in[2];
    const float* w       = (const float*)d_in[3];
    const float* centers = (const float*)d_in[4];
    const float* Rsrc    = (const float*)d_in[5];
    const float* Rdst    = (const float*)d_in[6];
    const float* W1      = (const float*)d_in[7];
    const float* b1      = (const float*)d_in[8];
    const float* W2      = (const float*)d_in[9];
    const float* b2      = (const float*)d_in[10];
    const float* W3      = (const float*)d_in[11];
    const float* b3      = (const float*)d_in[12];
    const float* Wg1     = (const float*)d_in[13];
    const float* bg1     = (const float*)d_in[14];
    const float* Wg2     = (const float*)d_in[15];
    const float* bg2     = (const float*)d_in[16];
    const int*   idx     = (const int*)d_in[17];
    float* out = (float*)d_out;

    cudaFuncSetAttribute(cg_kernel, cudaFuncAttributeMaxDynamicSharedMemorySize,
                         SMEM_CG_BYTES);

    gvec_kernel<<<Bb, 256>>>(xs, us, Wg1, bg1, Wg2, bg2);
    enc_kernel<<<dim3(Mm, Bb), 64>>>(xs, us, centers, idx,
                                     W1, b1, W2, b2, W3, b3, out);
    cg_kernel<<<64, 512, SMEM_CG_BYTES>>>(Rsrc, Rdst, out);
    dec_kernel<<<Qq/32, 256>>>(phi, w, out);
}

// round 13
// speedup vs baseline: 1.5774x; 1.0797x over previous
#include <cuda_runtime.h>
#include <cstdint>

#define Bb 8
#define Nn 2048
#define Mm 256
#define Qq 16384
#define Dd 32
#define Rr 16
#define Kk 16
#define Hh 64
#define LAM 5.0f
#define NITER 20
#define RAD 0.005859375f   // 1.5/256 exact in binary

// ---------------- scratch (device globals; no allocation allowed) ----------
__device__ float g_c0[Bb*Mm*Dd];     // c_loc only; gvec added inside cg
__device__ float g_c [Bb*Mm*Dd];

__device__ __forceinline__ float warp_sum(float v) {
#pragma unroll
    for (int o = 16; o; o >>= 1) v += __shfl_xor_sync(0xffffffffu, v, o);
    return v;
}

__device__ __forceinline__ unsigned smem_u32(const void* p) {
    unsigned a;
    asm("{ .reg .u64 t; cvta.to.shared.u64 t, %1; cvt.u32.u64 %0, t; }"
        : "=r"(a) : "l"(p));
    return a;
}

// store 4 bytes into peer CTA (rank) smem at the address corresponding to laddr
__device__ __forceinline__ void st_remote(unsigned laddr, unsigned rank, float v) {
    unsigned r;
    asm volatile("mapa.shared::cluster.u32 %0, %1, %2;" : "=r"(r) : "r"(laddr), "r"(rank));
    asm volatile("st.shared::cluster.f32 [%0], %1;" :: "r"(r), "f"(v) : "memory");
}

__device__ __forceinline__ void cluster_sync_() {
    asm volatile("barrier.cluster.arrive.aligned;" ::: "memory");  // release
    asm volatile("barrier.cluster.wait.aligned;"   ::: "memory");  // acquire
}

// ---------------- kernel 1: encoder (low-smem; W2 from L1-resident gmem) ----
__global__ __launch_bounds__(64) void enc_kernel(
    const float* __restrict__ xs, const float* __restrict__ us,
    const float* __restrict__ centers, const int* __restrict__ idx,
    const float* __restrict__ W1, const float* __restrict__ b1,
    const float* __restrict__ W2, const float* __restrict__ b2,
    const float* __restrict__ W3, const float* __restrict__ b3)
{
    __shared__ float sh1[16*68];    // h1[k][i], float4-aligned rows
    __shared__ float srel[16], su[16], sW1[128], shbar[64];
    int m = blockIdx.x, b = blockIdx.y, t = threadIdx.x;

    for (int i = t; i < 128; i += 64) sW1[i] = W1[i];
    if (t < 16) {
        int sidx = idx[m*Kk + t];
        srel[t] = (xs[b*Nn + sidx] - centers[m]) / RAD;
        su[t]   = us[b*Nn + sidx];
    }
    __syncthreads();

    {   // h1: thread t = hidden unit i
        float wa = sW1[t], wb = sW1[64+t], bb = b1[t];
#pragma unroll
        for (int k = 0; k < 16; k++)
            sh1[k*68 + t] = fmaxf(fmaf(srel[k], wa, fmaf(su[k], wb, bb)), 0.f);
    }
    __syncthreads();

    {   // h2 = relu(h1 @ W2 + b2); mean over k.  W2 columns via coalesced LDG.
        float acc[16];
        float bb = b2[t];
#pragma unroll
        for (int k = 0; k < 16; k++) acc[k] = bb;
#pragma unroll 4
        for (int i = 0; i < 64; i += 4) {
            float w0 = __ldg(&W2[(i+0)*64 + t]);
            float w1 = __ldg(&W2[(i+1)*64 + t]);
            float w2 = __ldg(&W2[(i+2)*64 + t]);
            float w3 = __ldg(&W2[(i+3)*64 + t]);
#pragma unroll
            for (int k = 0; k < 16; k++) {
                float4 hq = *(const float4*)&sh1[k*68 + i];
                acc[k] = fmaf(hq.x, w0, acc[k]);
                acc[k] = fmaf(hq.y, w1, acc[k]);
                acc[k] = fmaf(hq.z, w2, acc[k]);
                acc[k] = fmaf(hq.w, w3, acc[k]);
            }
        }
        float s = 0.f;
#pragma unroll
        for (int k = 0; k < 16; k++) s += fmaxf(acc[k], 0.f);
        shbar[t] = s * 0.0625f;
    }
    __syncthreads();

    if (t < 32) {
        float v = b3[t];
        for (int j = 0; j < 64; j++) v = fmaf(shbar[j], W3[j*Dd + t], v);
        g_c0[(b*Mm + m)*Dd + t] = v;   // c_loc only
    }
}

// ---------------- CG: sheaf Laplacian edge pass (R tiles in smem) -----------
__device__ __forceinline__ void edge_pass(
    const float* __restrict__ sRS, const float* __restrict__ sRD,
    const float* __restrict__ sV, float* __restrict__ sGs, float* __restrict__ sGd,
    float* __restrict__ sRe, int nE, int wid, int lane)
{
    int rho = lane >> 1, h = lane & 1;
    int d = lane;
    for (int el = wid; el < nE; el += 32) {
        const float* bs = sRS + el*528;
        const float* bd = sRD + el*528;
        const float* ps = sV + el*32 + 16*h;     // src half; dst at +32
        const float* rs_ = bs + rho*33 + 16*h;
        const float* rd_ = bd + rho*33 + 16*h;
        float a0 = 0.f, a1 = 0.f, a2 = 0.f, a3 = 0.f;
#pragma unroll
        for (int i = 0; i < 16; i += 4) {
            a0 = fmaf(rs_[i+0], ps[i+0], a0);
            a1 = fmaf(rs_[i+1], ps[i+1], a1);
            a2 = fmaf(rs_[i+2], ps[i+2], a2);
            a3 = fmaf(rs_[i+3], ps[i+3], a3);
            a0 = fmaf(rd_[i+0], -ps[32+i+0], a0);
            a1 = fmaf(rd_[i+1], -ps[32+i+1], a1);
            a2 = fmaf(rd_[i+2], -ps[32+i+2], a2);
            a3 = fmaf(rd_[i+3], -ps[32+i+3], a3);
        }
        float acc = (a0 + a1) + (a2 + a3);
        acc += __shfl_xor_sync(0xffffffffu, acc, 1);
        if (h == 0) sRe[el*16 + rho] = acc;
        __syncwarp();

        float g0 = 0.f, g1 = 0.f, q0a = 0.f, q1a = 0.f;
#pragma unroll
        for (int q = 0; q < 16; q += 2) {
            float r0v = sRe[el*16 + q];
            float r1v = sRe[el*16 + q + 1];
            g0  = fmaf(bs[q*33 + d],       r0v, g0);
            g1  = fmaf(bs[(q+1)*33 + d],   r1v, g1);
            q0a = fmaf(bd[q*33 + d],       r0v, q0a);
            q1a = fmaf(bd[(q+1)*33 + d],   r1v, q1a);
        }
        sGs[el*32 + d] = g0 + g1;
        sGd[el*32 + d] = q0a + q1a;
    }
}

// ---------------- kernel 2: single-sync CG + fused gvec (8x8 cluster) -------
// smem layout (float offsets); nE <= 33, nExt <= 34
#define SM_RS   0                        // 33*528 = 17424
#define SM_RD   17424
#define SM_RV   34848                    // r extended, 34*32 = 1088
#define SM_W    (SM_RV + 1088)           // w own, 1024
#define SM_S    (SM_W + 1024)            // s extended, 1088
#define SM_PP   (SM_S + 1088)            // p own, 1024
#define SM_X    (SM_PP + 1024)           // x own, 1024
#define SM_GS   (SM_X + 1024)            // 33*32 = 1056
#define SM_GD   (SM_GS + 1056)           // 1056
#define SM_RE   (SM_GD + 1056)           // 33*16 = 528
#define SM_RED  (SM_RE + 528)            // 32 gamma + 32 delta warp partials
#define SM_SC   (SM_RED + 64)            // [par][g:8|d:8] = 32
#define SM_WH   (SM_SC + 32)             // [par][L:32|R:32] = 128
#define SM_GP   (SM_WH + 128)            // gvec grp partials 16*64 = 1024
#define SM_GVL  (SM_GP + 1024)           // local gvec partial [64]
#define SM_GV   (SM_GVL + 64)            // incoming partials [8][64] = 512
#define SM_SG   (SM_GV + 512)            // sg [64]
#define SM_GVEC (SM_SG + 64)             // gvec [32]
#define SM_TOT_FLOATS (SM_GVEC + 32)
#define SMEM_CG_BYTES (SM_TOT_FLOATS * 4)

__global__ __launch_bounds__(1024, 1) __cluster_dims__(8, 1, 1)
void cg_kernel(const float* __restrict__ Rsrc, const float* __restrict__ Rdst,
               const float* __restrict__ xs, const float* __restrict__ us,
               const float* __restrict__ Wg1, const float* __restrict__ bg1,
               const float* __restrict__ Wg2, const float* __restrict__ bg2,
               float* __restrict__ out)
{
    extern __shared__ float sm[];
    float* sRS  = sm + SM_RS;
    float* sRD  = sm + SM_RD;
    float* sRV  = sm + SM_RV;
    float* sW   = sm + SM_W;
    float* sS   = sm + SM_S;
    float* sPP  = sm + SM_PP;
    float* sX   = sm + SM_X;
    float* sGs  = sm + SM_GS;
    float* sGd  = sm + SM_GD;
    float* sRe  = sm + SM_RE;
    float* sRed = sm + SM_RED;

    int t = threadIdx.x, wid = t >> 5, lane = t & 31;
    int blk = blockIdx.x;
    int b = blk >> 3, c = blk & 7;          // cluster = batch, rank = c
    int m0 = c * 32;
    int mLo = (c > 0) ? m0 - 1 : 0;
    int eLo = (c > 0) ? m0 - 1 : 0;
    int eHi = (c < 7) ? m0 + 31 : 254;
    int nE = eHi - eLo + 1;                 // 32 or 33
    int nExt = 32 + (c > 0 ? 1 : 0) + (c < 7 ? 1 : 0);
    int ownOff = (c > 0) ? 32 : 0;
    int rhOff = ownOff + 1024;              // right-halo offset in extended bufs

    unsigned smb = smem_u32(sm);

    // ---- gvec partials: this CTA handles sensors [c*256, c*256+256) ----
    {
        int h = t & 63, grp = t >> 6;       // grp 0..15
        const float* xp = xs + b*Nn + c*256 + grp*16;
        const float* up = us + b*Nn + c*256 + grp*16;
        float w0 = __ldg(&Wg1[h]), w1 = __ldg(&Wg1[Hh+h]), bb = __ldg(&bg1[h]);
        float acc = 0.f;
#pragma unroll
        for (int j = 0; j < 16; j++)
            acc += fmaxf(fmaf(xp[j], w0, fmaf(up[j], w1, bb)), 0.f);
        sm[SM_GP + grp*64 + h] = acc;
    }
    __syncthreads();
    if (t < 64) {
        float s = 0.f;
#pragma unroll
        for (int g = 0; g < 16; g++) s += sm[SM_GP + g*64 + t];
        sm[SM_GVL + t] = s;
    }
    __syncthreads();
    if (t < 512) {                          // push my 64 partials to all ranks
        int rk = t >> 6, hh = t & 63;
        st_remote(smb + (SM_GV + c*64 + hh)*4, (unsigned)rk, sm[SM_GVL + hh]);
    }

    // ---- load R tiles into padded smem (overlaps with gvec exchange) ----
    for (int i = t; i < nE*512; i += 1024) {
        int el = i >> 9, rem = i & 511;
        int rho = rem >> 5, d = rem & 31;
        int g = (eLo + el)*512 + rem;
        sRS[el*528 + rho*33 + d] = Rsrc[g];
        sRD[el*528 + rho*33 + d] = Rdst[g];
    }
    // c_loc extended into sRV (gvec added after sync)
    const float* c0b = g_c0 + b*Mm*Dd;
    for (int i = t; i < nExt*32; i += 1024) sRV[i] = c0b[mLo*32 + i];
    cluster_sync_();

    // ---- finish gvec: reduce 8 rank partials, project to d ----
    if (t < 64) {
        float s = 0.f;
#pragma unroll
        for (int j = 0; j < 8; j++) s += sm[SM_GV + j*64 + t];
        sm[SM_SG + t] = s * (1.0f/Nn);
    }
    __syncthreads();
    if (t < 32) {
        float a = __ldg(&bg2[t]);
        for (int hh = 0; hh < Hh; hh++)
            a = fmaf(sm[SM_SG + hh], __ldg(&Wg2[hh*Dd + t]), a);
        sm[SM_GVEC + t] = a;
    }
    __syncthreads();
    for (int i = t; i < nExt*32; i += 1024) sRV[i] += sm[SM_GVEC + (i & 31)];
    __syncthreads();

    // ---- prologue: x = c0; write c0 out; r0 = -LAM*L(c0) ----
    edge_pass(sRS, sRD, sRV, sGs, sGd, sRe, nE, wid, lane);
    __syncthreads();
    {
        int dd = t & 31, m = m0 + (t >> 5);
        float gs = (m <= Mm-2) ? sGs[(m - eLo)*32 + dd] : 0.f;
        float gd = (m >= 1)    ? sGd[(m - 1 - eLo)*32 + dd] : 0.f;
        float c0v = sRV[ownOff + t];
        sX[t] = c0v;
        out[Bb*Qq + (b*Mm + m0)*32 + t] = c0v;   // c0 output segment
        sRV[ownOff + t] = -LAM * (gs - gd);      // r0 own
    }
    __syncthreads();
    // push r0 boundary rows into neighbors' WH parity-1 slots
    if (c > 0 && t < 32)
        st_remote(smb + (SM_WH + 64 + 32 + t)*4, (unsigned)(c-1), sRV[ownOff + t]);
    if (c < 7 && t >= 32 && t < 64) { int l = t - 32;
        st_remote(smb + (SM_WH + 64 + l)*4, (unsigned)(c+1), sRV[ownOff + 31*32 + l]); }
    cluster_sync_();
    if (c > 0 && t < 32)               sRV[t] = sm[SM_WH + 64 + t];
    if (c < 7 && t >= 32 && t < 64) {  int l = t - 32;
                                       sRV[rhOff + l] = sm[SM_WH + 64 + 32 + l]; }
    __syncthreads();

    float gamma_prev = 1.f, alpha_prev = 1.f;
    for (int k = 0; k < NITER; k++) {
        int par = k & 1;
        // ---- w = A r (own nodes); gamma = r.r, delta = r.w ----
        edge_pass(sRS, sRD, sRV, sGs, sGd, sRe, nE, wid, lane);
        __syncthreads();
        {
            int dd = t & 31, m = m0 + (t >> 5);
            float gs = (m <= Mm-2) ? sGs[(m - eLo)*32 + dd] : 0.f;
            float gd = (m >= 1)    ? sGd[(m - 1 - eLo)*32 + dd] : 0.f;
            float rv = sRV[ownOff + t];
            float wv = fmaf(LAM, gs - gd, rv);
            sW[t] = wv;
            float g = warp_sum(rv * rv);
            float d = warp_sum(rv * wv);
            if (lane == 0) { sRed[wid] = g; sRed[32 + wid] = d; }
        }
        __syncthreads();
        // ---- pushes: scalars (warp all-reduce) + w boundary rows ----
        if (wid == 0) {
            float tot = warp_sum(sRed[lane]);
            if (lane < 8) st_remote(smb + (SM_SC + par*16 + c)*4, (unsigned)lane, tot);
        } else if (wid == 1) {
            float tot = warp_sum(sRed[32 + lane]);
            if (lane < 8) st_remote(smb + (SM_SC + par*16 + 8 + c)*4, (unsigned)lane, tot);
        }
        if (c > 0 && t >= 64 && t < 96) { int l = t - 64;
            st_remote(smb + (SM_WH + par*64 + 32 + l)*4, (unsigned)(c-1), sW[l]); }
        if (c < 7 && t >= 96 && t < 128) { int l = t - 96;
            st_remote(smb + (SM_WH + par*64 + l)*4, (unsigned)(c+1), sW[31*32 + l]); }
        cluster_sync_();

        // ---- scalars (identical on all CTAs) ----
        float gamma = 0.f, delta = 0.f;
#pragma unroll
        for (int j = 0; j < 8; j++) { gamma += sm[SM_SC + par*16 + j];
                                      delta += sm[SM_SC + par*16 + 8 + j]; }
        float beta  = (k == 0) ? 0.f : gamma / (gamma_prev + 1e-12f);
        float den   = (k == 0) ? delta : delta - beta * gamma / alpha_prev;
        float alpha = gamma / (den + 1e-12f);

        // ---- local updates: s,r extended; p,x own ----
        for (int i = t; i < nExt*32; i += 1024) {
            int io = i - ownOff;
            float wv;
            if (io >= 0 && io < 1024)      wv = sW[io];
            else if (io < 0)               wv = sm[SM_WH + par*64 + i];
            else                           wv = sm[SM_WH + par*64 + 32 + (io - 1024)];
            float sv = (k == 0) ? wv : fmaf(beta, sS[i], wv);
            sS[i] = sv;
            if (io >= 0 && io < 1024) {
                float rold = sRV[i];
                float pv = (k == 0) ? rold : fmaf(beta, sPP[io], rold);
                sPP[io] = pv;
                sX[io] = fmaf(alpha, pv, sX[io]);
            }
            sRV[i] = fmaf(-alpha, sv, sRV[i]);
        }
        __syncthreads();

        gamma_prev = gamma;
        alpha_prev = alpha;
    }

    // final x -> g_c and out c segment
    {
        float v = sX[t];
        int o = (b*Mm + m0)*32 + t;
        g_c[o] = v;
        out[Bb*Qq + Bb*Mm*Dd + o] = v;
    }
}

// ---------------- kernel 3: sparse decode (hoisted predicated loads) --------
__global__ __launch_bounds__(256) void dec_kernel(
    const float* __restrict__ phi, const float* __restrict__ w,
    float* __restrict__ out)
{
    __shared__ float sc[3*8*32];
    __shared__ float sw[3*32];
    int blk = blockIdx.x, t = threadIdx.x;
    int q0 = blk * 32;
    int g = blk >> 1;                  // 64-q group shares an m-center
    int mlist[3] = {0, 0, 0};
    int nm = 0;
#pragma unroll
    for (int dm = -1; dm <= 1; dm++) {
        int mm = g + dm;
        if (mm >= 0 && mm < Mm) mlist[nm++] = mm;
    }
    for (int i = t; i < nm*256; i += 256) {
        int mi = i >> 8, rem = i & 255;
        int bidx = rem >> 5, d = rem & 31;
        sc[i] = g_c[(bidx*Mm + mlist[mi])*Dd + d];
    }
    if (t < nm*32) {
        int mi = t >> 5, ql = t & 31;
        sw[t] = w[mlist[mi]*Qq + q0 + ql];
    }
    __syncthreads();

    int ql = t >> 3, dq = t & 7;       // 8 threads per q, 4 d each
    int q = q0 + ql;

    // hoist all (up to 3) phi loads: independent, front-batched
    float4 pv[3];
    float wq[3];
#pragma unroll
    for (int mi = 0; mi < 3; mi++) {
        if (mi < nm) {
            pv[mi] = *(const float4*)(phi + ((size_t)mlist[mi]*Qq + q)*Dd + dq*4);
            wq[mi] = sw[mi*32 + ql];
        } else {
            pv[mi] = make_float4(0.f, 0.f, 0.f, 0.f);
            wq[mi] = 0.f;
        }
    }

    float s[8];
#pragma unroll
    for (int bidx = 0; bidx < 8; bidx++) s[bidx] = 0.f;

#pragma unroll
    for (int mi = 0; mi < 3; mi++) {
        int ms = (mi < nm) ? mi : 0;   // valid smem index; wq=0 kills the term
#pragma unroll
        for (int bidx = 0; bidx < 8; bidx++) {
            const float* cc = &sc[(ms*8 + bidx)*32 + dq*4];
            float dot = pv[mi].x*cc[0] + pv[mi].y*cc[1]
                      + pv[mi].z*cc[2] + pv[mi].w*cc[3];
            s[bidx] = fmaf(wq[mi], dot, s[bidx]);
        }
    }
#pragma unroll
    for (int bidx = 0; bidx < 8; bidx++) {
        s[bidx] += __shfl_xor_sync(0xffffffffu, s[bidx], 1);
        s[bidx] += __shfl_xor_sync(0xffffffffu, s[bidx], 2);
        s[bidx] += __shfl_xor_sync(0xffffffffu, s[bidx], 4);
    }
    if (dq == 0) {
#pragma unroll
        for (int bidx = 0; bidx < 8; bidx++)
            out[bidx*Qq + q] = s[bidx];
    }
}

// ---------------- launch ----------------------------------------------------
extern "C" void kernel_launch(void* const* d_in, const int* in_sizes, int n_in,
                              void* d_out, int out_size)
{
    (void)in_sizes; (void)n_in; (void)out_size;
    const float* xs      = (const float*)d_in[0];
    const float* us      = (const float*)d_in[1];
    const float* phi     = (const float*)d_in[2];
    const float* w       = (const float*)d_in[3];
    const float* centers = (const float*)d_in[4];
    const float* Rsrc    = (const float*)d_in[5];
    const float* Rdst    = (const float*)d_in[6];
    const float* W1      = (const float*)d_in[7];
    const float* b1      = (const float*)d_in[8];
    const float* W2      = (const float*)d_in[9];
    const float* b2      = (const float*)d_in[10];
    const float* W3      = (const float*)d_in[11];
    const float* b3      = (const float*)d_in[12];
    const float* Wg1     = (const float*)d_in[13];
    const float* bg1     = (const float*)d_in[14];
    const float* Wg2     = (const float*)d_in[15];
    const float* bg2     = (const float*)d_in[16];
    const int*   idx     = (const int*)d_in[17];
    float* out = (float*)d_out;

    cudaFuncSetAttribute(cg_kernel, cudaFuncAttributeMaxDynamicSharedMemorySize,
                         SMEM_CG_BYTES);

    enc_kernel<<<dim3(Mm, Bb), 64>>>(xs, us, centers, idx,
                                     W1, b1, W2, b2, W3, b3);
    cg_kernel<<<64, 1024, SMEM_CG_BYTES>>>(Rsrc, Rdst, xs, us,
                                           Wg1, bg1, Wg2, bg2, out);
    dec_kernel<<<Qq/32, 256>>>(phi, w, out);
}

// round 14
// speedup vs baseline: 1.6126x; 1.0223x over previous
#include <cuda_runtime.h>
#include <cstdint>

#define Bb 8
#define Nn 2048
#define Mm 256
#define Qq 16384
#define Dd 32
#define Rr 16
#define Kk 16
#define Hh 64
#define LAM 5.0f
#define NITER 20
#define RAD 0.005859375f   // 1.5/256 exact in binary

// ---------------- scratch (device globals; no allocation allowed) ----------
__device__ float g_c0[Bb*Mm*Dd];     // c_loc only; gvec added inside cg
__device__ float g_c [Bb*Mm*Dd];

__device__ __forceinline__ float warp_sum(float v) {
#pragma unroll
    for (int o = 16; o; o >>= 1) v += __shfl_xor_sync(0xffffffffu, v, o);
    return v;
}

__device__ __forceinline__ unsigned smem_u32(const void* p) {
    unsigned a;
    asm("{ .reg .u64 t; cvta.to.shared.u64 t, %1; cvt.u32.u64 %0, t; }"
        : "=r"(a) : "l"(p));
    return a;
}

// store 4 bytes into peer CTA (rank) smem at the address corresponding to laddr
__device__ __forceinline__ void st_remote(unsigned laddr, unsigned rank, float v) {
    unsigned r;
    asm volatile("mapa.shared::cluster.u32 %0, %1, %2;" : "=r"(r) : "r"(laddr), "r"(rank));
    asm volatile("st.shared::cluster.f32 [%0], %1;" :: "r"(r), "f"(v) : "memory");
}

__device__ __forceinline__ void cluster_sync_() {
    asm volatile("barrier.cluster.arrive.aligned;" ::: "memory");  // release
    asm volatile("barrier.cluster.wait.aligned;"   ::: "memory");  // acquire
}

// ---------------- kernel 1: encoder (128 thr: thread = (j, k-half)) ---------
__global__ __launch_bounds__(128) void enc_kernel(
    const float* __restrict__ xs, const float* __restrict__ us,
    const float* __restrict__ centers, const int* __restrict__ idx,
    const float* __restrict__ W1, const float* __restrict__ b1,
    const float* __restrict__ W2, const float* __restrict__ b2,
    const float* __restrict__ W3, const float* __restrict__ b3)
{
    __shared__ float sh1[16*68];    // h1[k][i], float4-aligned rows
    __shared__ float srel[16], su[16], sW1[128];
    __shared__ float spart[2][64];  // per-half relu-sum over k
    __shared__ float shbar[64];
    int m = blockIdx.x, b = blockIdx.y, t = threadIdx.x;
    int j = t & 63, half = t >> 6;

    if (t < 128) sW1[t] = W1[t];
    if (t < 16) {
        int sidx = idx[m*Kk + t];
        srel[t] = (xs[b*Nn + sidx] - centers[m]) / RAD;
        su[t]   = us[b*Nn + sidx];
    }
    __syncthreads();

    {   // h1: thread (j, half) computes k = half*8 + kk for unit j
        float wa = sW1[j], wb = sW1[64+j], bb = b1[j];
#pragma unroll
        for (int kk = 0; kk < 8; kk++) {
            int k = half*8 + kk;
            sh1[k*68 + j] = fmaxf(fmaf(srel[k], wa, fmaf(su[k], wb, bb)), 0.f);
        }
    }
    __syncthreads();

    {   // h2 = relu(h1 @ W2 + b2) for this thread's 8 k; partial mean
        float acc[8];
        float bb = b2[j];
#pragma unroll
        for (int kk = 0; kk < 8; kk++) acc[kk] = bb;
        const float* h1base = sh1 + half*8*68;
#pragma unroll 4
        for (int i = 0; i < 64; i += 4) {
            float w0 = __ldg(&W2[(i+0)*64 + j]);
            float w1 = __ldg(&W2[(i+1)*64 + j]);
            float w2 = __ldg(&W2[(i+2)*64 + j]);
            float w3 = __ldg(&W2[(i+3)*64 + j]);
#pragma unroll
            for (int kk = 0; kk < 8; kk++) {
                float4 hq = *(const float4*)&h1base[kk*68 + i];
                acc[kk] = fmaf(hq.x, w0, acc[kk]);
                acc[kk] = fmaf(hq.y, w1, acc[kk]);
                acc[kk] = fmaf(hq.z, w2, acc[kk]);
                acc[kk] = fmaf(hq.w, w3, acc[kk]);
            }
        }
        float s = 0.f;
#pragma unroll
        for (int kk = 0; kk < 8; kk++) s += fmaxf(acc[kk], 0.f);
        spart[half][j] = s;
    }
    __syncthreads();
    if (t < 64) shbar[t] = (spart[0][t] + spart[1][t]) * 0.0625f;
    __syncthreads();

    if (t < 32) {
        float v = b3[t];
        for (int jj = 0; jj < 64; jj++) v = fmaf(shbar[jj], W3[jj*Dd + t], v);
        g_c0[(b*Mm + m)*Dd + t] = v;   // c_loc only
    }
}

// ---------------- CG: sheaf Laplacian edge pass (R tiles in smem) -----------
__device__ __forceinline__ void edge_pass(
    const float* __restrict__ sRS, const float* __restrict__ sRD,
    const float* __restrict__ sV, float* __restrict__ sGs, float* __restrict__ sGd,
    float* __restrict__ sRe, int nE, int wid, int lane)
{
    int rho = lane >> 1, h = lane & 1;
    int d = lane;
    for (int el = wid; el < nE; el += 32) {
        const float* bs = sRS + el*528;
        const float* bd = sRD + el*528;
        const float* ps = sV + el*32 + 16*h;     // src half; dst at +32
        const float* rs_ = bs + rho*33 + 16*h;
        const float* rd_ = bd + rho*33 + 16*h;
        float a0 = 0.f, a1 = 0.f, a2 = 0.f, a3 = 0.f;
#pragma unroll
        for (int i = 0; i < 16; i += 4) {
            a0 = fmaf(rs_[i+0], ps[i+0], a0);
            a1 = fmaf(rs_[i+1], ps[i+1], a1);
            a2 = fmaf(rs_[i+2], ps[i+2], a2);
            a3 = fmaf(rs_[i+3], ps[i+3], a3);
            a0 = fmaf(rd_[i+0], -ps[32+i+0], a0);
            a1 = fmaf(rd_[i+1], -ps[32+i+1], a1);
            a2 = fmaf(rd_[i+2], -ps[32+i+2], a2);
            a3 = fmaf(rd_[i+3], -ps[32+i+3], a3);
        }
        float acc = (a0 + a1) + (a2 + a3);
        acc += __shfl_xor_sync(0xffffffffu, acc, 1);
        if (h == 0) sRe[el*16 + rho] = acc;
        __syncwarp();

        float g0 = 0.f, g1 = 0.f, q0a = 0.f, q1a = 0.f;
#pragma unroll
        for (int q = 0; q < 16; q += 2) {
            float r0v = sRe[el*16 + q];
            float r1v = sRe[el*16 + q + 1];
            g0  = fmaf(bs[q*33 + d],       r0v, g0);
            g1  = fmaf(bs[(q+1)*33 + d],   r1v, g1);
            q0a = fmaf(bd[q*33 + d],       r0v, q0a);
            q1a = fmaf(bd[(q+1)*33 + d],   r1v, q1a);
        }
        sGs[el*32 + d] = g0 + g1;
        sGd[el*32 + d] = q0a + q1a;
    }
}

// ---------------- kernel 2: single-sync CG + fused gvec (8x8 cluster) -------
// smem layout (float offsets); nE <= 33, nExt <= 34
#define SM_RS   0                        // 33*528 = 17424
#define SM_RD   17424
#define SM_RV   34848                    // r extended, 34*32 = 1088
#define SM_W    (SM_RV + 1088)           // w own, 1024
#define SM_S    (SM_W + 1024)            // s extended, 1088
#define SM_PP   (SM_S + 1088)            // p own, 1024
#define SM_X    (SM_PP + 1024)           // x own, 1024
#define SM_GS   (SM_X + 1024)            // 33*32 = 1056
#define SM_GD   (SM_GS + 1056)           // 1056
#define SM_RE   (SM_GD + 1056)           // 33*16 = 528
#define SM_RED  (SM_RE + 528)            // 32 gamma + 32 delta warp partials
#define SM_SC   (SM_RED + 64)            // [par][g:8|d:8] = 32
#define SM_WH   (SM_SC + 32)             // [par][L:32|R:32] = 128
#define SM_GP   (SM_WH + 128)            // gvec grp partials 16*64 = 1024
#define SM_GVL  (SM_GP + 1024)           // local gvec partial [64]
#define SM_GV   (SM_GVL + 64)            // incoming partials [8][64] = 512
#define SM_SG   (SM_GV + 512)            // sg [64]
#define SM_GVEC (SM_SG + 64)             // gvec [32]
#define SM_TOT_FLOATS (SM_GVEC + 32)
#define SMEM_CG_BYTES (SM_TOT_FLOATS * 4)

__global__ __launch_bounds__(1024, 1) __cluster_dims__(8, 1, 1)
void cg_kernel(const float* __restrict__ Rsrc, const float* __restrict__ Rdst,
               const float* __restrict__ xs, const float* __restrict__ us,
               const float* __restrict__ Wg1, const float* __restrict__ bg1,
               const float* __restrict__ Wg2, const float* __restrict__ bg2,
               float* __restrict__ out)
{
    extern __shared__ float sm[];
    float* sRS  = sm + SM_RS;
    float* sRD  = sm + SM_RD;
    float* sRV  = sm + SM_RV;
    float* sW   = sm + SM_W;
    float* sS   = sm + SM_S;
    float* sPP  = sm + SM_PP;
    float* sX   = sm + SM_X;
    float* sGs  = sm + SM_GS;
    float* sGd  = sm + SM_GD;
    float* sRe  = sm + SM_RE;
    float* sRed = sm + SM_RED;

    int t = threadIdx.x, wid = t >> 5, lane = t & 31;
    int blk = blockIdx.x;
    int b = blk >> 3, c = blk & 7;          // cluster = batch, rank = c
    int m0 = c * 32;
    int mLo = (c > 0) ? m0 - 1 : 0;
    int eLo = (c > 0) ? m0 - 1 : 0;
    int eHi = (c < 7) ? m0 + 31 : 254;
    int nE = eHi - eLo + 1;                 // 32 or 33
    int nExt = 32 + (c > 0 ? 1 : 0) + (c < 7 ? 1 : 0);
    int ownOff = (c > 0) ? 32 : 0;
    int rhOff = ownOff + 1024;              // right-halo offset in extended bufs

    unsigned smb = smem_u32(sm);

    // ---- gvec partials: this CTA handles sensors [c*256, c*256+256) ----
    {
        int h = t & 63, grp = t >> 6;       // grp 0..15
        const float* xp = xs + b*Nn + c*256 + grp*16;
        const float* up = us + b*Nn + c*256 + grp*16;
        float w0 = __ldg(&Wg1[h]), w1 = __ldg(&Wg1[Hh+h]), bb = __ldg(&bg1[h]);
        float acc = 0.f;
#pragma unroll
        for (int j = 0; j < 16; j++)
            acc += fmaxf(fmaf(xp[j], w0, fmaf(up[j], w1, bb)), 0.f);
        sm[SM_GP + grp*64 + h] = acc;
    }
    __syncthreads();
    if (t < 64) {
        float s = 0.f;
#pragma unroll
        for (int g = 0; g < 16; g++) s += sm[SM_GP + g*64 + t];
        sm[SM_GVL + t] = s;
    }
    __syncthreads();
    if (t < 512) {                          // push my 64 partials to all ranks
        int rk = t >> 6, hh = t & 63;
        st_remote(smb + (SM_GV + c*64 + hh)*4, (unsigned)rk, sm[SM_GVL + hh]);
    }

    // ---- load R tiles into padded smem (overlaps with gvec exchange) ----
    for (int i = t; i < nE*512; i += 1024) {
        int el = i >> 9, rem = i & 511;
        int rho = rem >> 5, d = rem & 31;
        int g = (eLo + el)*512 + rem;
        sRS[el*528 + rho*33 + d] = Rsrc[g];
        sRD[el*528 + rho*33 + d] = Rdst[g];
    }
    // c_loc extended into sRV (gvec added after sync)
    const float* c0b = g_c0 + b*Mm*Dd;
    for (int i = t; i < nExt*32; i += 1024) sRV[i] = c0b[mLo*32 + i];
    cluster_sync_();

    // ---- finish gvec: reduce 8 rank partials, project to d ----
    if (t < 64) {
        float s = 0.f;
#pragma unroll
        for (int j = 0; j < 8; j++) s += sm[SM_GV + j*64 + t];
        sm[SM_SG + t] = s * (1.0f/Nn);
    }
    __syncthreads();
    if (t < 32) {
        float a = __ldg(&bg2[t]);
        for (int hh = 0; hh < Hh; hh++)
            a = fmaf(sm[SM_SG + hh], __ldg(&Wg2[hh*Dd + t]), a);
        sm[SM_GVEC + t] = a;
    }
    __syncthreads();
    for (int i = t; i < nExt*32; i += 1024) sRV[i] += sm[SM_GVEC + (i & 31)];
    __syncthreads();

    // ---- prologue: x = c0; write c0 out; r0 = -LAM*L(c0) ----
    edge_pass(sRS, sRD, sRV, sGs, sGd, sRe, nE, wid, lane);
    __syncthreads();
    {
        int dd = t & 31, m = m0 + (t >> 5);
        float gs = (m <= Mm-2) ? sGs[(m - eLo)*32 + dd] : 0.f;
        float gd = (m >= 1)    ? sGd[(m - 1 - eLo)*32 + dd] : 0.f;
        float c0v = sRV[ownOff + t];
        sX[t] = c0v;
        out[Bb*Qq + (b*Mm + m0)*32 + t] = c0v;   // c0 output segment
        sRV[ownOff + t] = -LAM * (gs - gd);      // r0 own
    }
    __syncthreads();
    // push r0 boundary rows into neighbors' WH parity-1 slots
    if (c > 0 && t < 32)
        st_remote(smb + (SM_WH + 64 + 32 + t)*4, (unsigned)(c-1), sRV[ownOff + t]);
    if (c < 7 && t >= 32 && t < 64) { int l = t - 32;
        st_remote(smb + (SM_WH + 64 + l)*4, (unsigned)(c+1), sRV[ownOff + 31*32 + l]); }
    cluster_sync_();
    if (c > 0 && t < 32)               sRV[t] = sm[SM_WH + 64 + t];
    if (c < 7 && t >= 32 && t < 64) {  int l = t - 32;
                                       sRV[rhOff + l] = sm[SM_WH + 64 + 32 + l]; }
    __syncthreads();

    float gamma_prev = 1.f, alpha_prev = 1.f;
    for (int k = 0; k < NITER; k++) {
        int par = k & 1;
        // ---- w = A r (own nodes); gamma = r.r, delta = r.w ----
        edge_pass(sRS, sRD, sRV, sGs, sGd, sRe, nE, wid, lane);
        __syncthreads();
        {
            int dd = t & 31, m = m0 + (t >> 5);
            float gs = (m <= Mm-2) ? sGs[(m - eLo)*32 + dd] : 0.f;
            float gd = (m >= 1)    ? sGd[(m - 1 - eLo)*32 + dd] : 0.f;
            float rv = sRV[ownOff + t];
            float wv = fmaf(LAM, gs - gd, rv);
            sW[t] = wv;
            float g = warp_sum(rv * rv);
            float d = warp_sum(rv * wv);
            if (lane == 0) { sRed[wid] = g; sRed[32 + wid] = d; }
        }
        __syncthreads();
        // ---- pushes: scalars (warp all-reduce) + w boundary rows ----
        if (wid == 0) {
            float tot = warp_sum(sRed[lane]);
            if (lane < 8) st_remote(smb + (SM_SC + par*16 + c)*4, (unsigned)lane, tot);
        } else if (wid == 1) {
            float tot = warp_sum(sRed[32 + lane]);
            if (lane < 8) st_remote(smb + (SM_SC + par*16 + 8 + c)*4, (unsigned)lane, tot);
        }
        if (c > 0 && t >= 64 && t < 96) { int l = t - 64;
            st_remote(smb + (SM_WH + par*64 + 32 + l)*4, (unsigned)(c-1), sW[l]); }
        if (c < 7 && t >= 96 && t < 128) { int l = t - 96;
            st_remote(smb + (SM_WH + par*64 + l)*4, (unsigned)(c+1), sW[31*32 + l]); }
        cluster_sync_();

        // ---- scalars (identical on all CTAs) ----
        float gamma = 0.f, delta = 0.f;
#pragma unroll
        for (int j = 0; j < 8; j++) { gamma += sm[SM_SC + par*16 + j];
                                      delta += sm[SM_SC + par*16 + 8 + j]; }
        float beta  = (k == 0) ? 0.f : gamma / (gamma_prev + 1e-12f);
        float den   = (k == 0) ? delta : delta - beta * gamma / alpha_prev;
        float alpha = gamma / (den + 1e-12f);

        // ---- local updates: s,r extended; p,x own ----
        for (int i = t; i < nExt*32; i += 1024) {
            int io = i - ownOff;
            float wv;
            if (io >= 0 && io < 1024)      wv = sW[io];
            else if (io < 0)               wv = sm[SM_WH + par*64 + i];
            else                           wv = sm[SM_WH + par*64 + 32 + (io - 1024)];
            float sv = (k == 0) ? wv : fmaf(beta, sS[i], wv);
            sS[i] = sv;
            if (io >= 0 && io < 1024) {
                float rold = sRV[i];
                float pv = (k == 0) ? rold : fmaf(beta, sPP[io], rold);
                sPP[io] = pv;
                sX[io] = fmaf(alpha, pv, sX[io]);
            }
            sRV[i] = fmaf(-alpha, sv, sRV[i]);
        }
        __syncthreads();

        gamma_prev = gamma;
        alpha_prev = alpha;
    }

    // final x -> g_c and out c segment
    {
        float v = sX[t];
        int o = (b*Mm + m0)*32 + t;
        g_c[o] = v;
        out[Bb*Qq + Bb*Mm*Dd + o] = v;
    }
}

// ---------------- kernel 3: sparse decode (16 thr/q, float2 loads) ----------
__global__ __launch_bounds__(256) void dec_kernel(
    const float* __restrict__ phi, const float* __restrict__ w,
    float* __restrict__ out)
{
    __shared__ float sc[3*8*32];
    __shared__ float sw[3*16];
    int blk = blockIdx.x, t = threadIdx.x;
    int q0 = blk * 16;
    int g = blk >> 2;                  // 64-q group shares an m-center
    int mlist[3] = {0, 0, 0};
    int nm = 0;
#pragma unroll
    for (int dm = -1; dm <= 1; dm++) {
        int mm = g + dm;
        if (mm >= 0 && mm < Mm) mlist[nm++] = mm;
    }
    for (int i = t; i < nm*256; i += 256) {
        int mi = i >> 8, rem = i & 255;
        int bidx = rem >> 5, d = rem & 31;
        sc[i] = g_c[(bidx*Mm + mlist[mi])*Dd + d];
    }
    if (t < nm*16) {
        int mi = t >> 4, ql = t & 15;
        sw[t] = w[mlist[mi]*Qq + q0 + ql];
    }
    __syncthreads();

    int ql = t >> 4, dq = t & 15;      // 16 threads per q, 2 d each
    int q = q0 + ql;

    // hoist all (up to 3) phi loads: independent, front-batched
    float2 pv[3];
    float wq[3];
#pragma unroll
    for (int mi = 0; mi < 3; mi++) {
        if (mi < nm) {
            pv[mi] = *(const float2*)(phi + ((size_t)mlist[mi]*Qq + q)*Dd + dq*2);
            wq[mi] = sw[mi*16 + ql];
        } else {
            pv[mi] = make_float2(0.f, 0.f);
            wq[mi] = 0.f;
        }
    }

    float s[8];
#pragma unroll
    for (int bidx = 0; bidx < 8; bidx++) s[bidx] = 0.f;

#pragma unroll
    for (int mi = 0; mi < 3; mi++) {
        int ms = (mi < nm) ? mi : 0;   // valid smem index; wq=0 kills the term
#pragma unroll
        for (int bidx = 0; bidx < 8; bidx++) {
            const float* cc = &sc[(ms*8 + bidx)*32 + dq*2];
            float dot = pv[mi].x*cc[0] + pv[mi].y*cc[1];
            s[bidx] = fmaf(wq[mi], dot, s[bidx]);
        }
    }
#pragma unroll
    for (int bidx = 0; bidx < 8; bidx++) {
        s[bidx] += __shfl_xor_sync(0xffffffffu, s[bidx], 1);
        s[bidx] += __shfl_xor_sync(0xffffffffu, s[bidx], 2);
        s[bidx] += __shfl_xor_sync(0xffffffffu, s[bidx], 4);
        s[bidx] += __shfl_xor_sync(0xffffffffu, s[bidx], 8);
    }
    if (dq == 0) {
#pragma unroll
        for (int bidx = 0; bidx < 8; bidx++)
            out[bidx*Qq + q] = s[bidx];
    }
}

// ---------------- launch ----------------------------------------------------
extern "C" void kernel_launch(void* const* d_in, const int* in_sizes, int n_in,
                              void* d_out, int out_size)
{
    (void)in_sizes; (void)n_in; (void)out_size;
    const float* xs      = (const float*)d_in[0];
    const float* us      = (const float*)d_in[1];
    const float* phi     = (const float*)d_in[2];
    const float* w       = (const float*)d_in[3];
    const float* centers = (const float*)d_in[4];
    const float* Rsrc    = (const float*)d_in[5];
    const float* Rdst    = (const float*)d_in[6];
    const float* W1      = (const float*)d_in[7];
    const float* b1      = (const float*)d_in[8];
    const float* W2      = (const float*)d_in[9];
    const float* b2      = (const float*)d_in[10];
    const float* W3      = (const float*)d_in[11];
    const float* b3      = (const float*)d_in[12];
    const float* Wg1     = (const float*)d_in[13];
    const float* bg1     = (const float*)d_in[14];
    const float* Wg2     = (const float*)d_in[15];
    const float* bg2     = (const float*)d_in[16];
    const int*   idx     = (const int*)d_in[17];
    float* out = (float*)d_out;

    cudaFuncSetAttribute(cg_kernel, cudaFuncAttributeMaxDynamicSharedMemorySize,
                         SMEM_CG_BYTES);

    enc_kernel<<<dim3(Mm, Bb), 128>>>(xs, us, centers, idx,
                                      W1, b1, W2, b2, W3, b3);
    cg_kernel<<<64, 1024, SMEM_CG_BYTES>>>(Rsrc, Rdst, xs, us,
                                           Wg1, bg1, Wg2, bg2, out);
    dec_kernel<<<Qq/16, 256>>>(phi, w, out);
}